// round 9
// baseline (speedup 1.0000x reference)
#include <cuda_runtime.h>
#include <cuda_bf16.h>

// PeriodicConvOp == parity-scrambled 3x3 conv.
// x: [8,4,512,512] f32, weight: [32,36] f32, out: [8,8,512,512] f32.
//
// For flat channel n in [0,32): g = n>>3 (gy=g>>1, gx=g&1), o = n&7:
//   conv[n](h,w) = sum_{cin,ky,kx} W[(g*8+o)*36 + cin*9+ky*3+kx]
//                  * x[b,cin, 2h+gy+ky-1, 2w+gx+kx-1]
//   out[b, n>>2, 2h + ((n>>1)&1), 2w + (n&1)] = conv[n](h,w)
//
// 256 threads: m = tid&3 (o-pair {2m,2m+1} -> j=0/1 f32x2 lanes),
// tcx = (tid>>2)&3 (4 superpixels), ty = tid>>4 (0..15).
// Tile: 16x16 superpixels (32x32 out px) per block.
//
// R8: best-measured operand path (duplicated {v,v} tile, direct LDS.128 ->
// FFMA2, row-major single-live-row schedule) + division-free warp-per-row
// staging + occupancy 4 (64-reg target, 32 warps/SM).

#define PITCH 34   // input tile row length in (duplicated) float2 elements

__device__ __forceinline__ void ffma2(unsigned long long& d,
                                      unsigned long long a,
                                      unsigned long long b) {
    asm("fma.rn.f32x2 %0, %1, %2, %0;" : "+l"(d) : "l"(a), "l"(b));
}

// load 10 consecutive packed {v,v} positions (5x LDS.128)
__device__ __forceinline__ void ldrow(unsigned long long* r, const float2* p) {
    const ulonglong2 a = *(const ulonglong2*)(p);
    const ulonglong2 b = *(const ulonglong2*)(p + 2);
    const ulonglong2 c = *(const ulonglong2*)(p + 4);
    const ulonglong2 d = *(const ulonglong2*)(p + 6);
    const ulonglong2 e = *(const ulonglong2*)(p + 8);
    r[0] = a.x; r[1] = a.y; r[2] = b.x; r[3] = b.y; r[4] = c.x;
    r[5] = c.y; r[6] = d.x; r[7] = d.y; r[8] = e.x; r[9] = e.y;
}

__global__ __launch_bounds__(256, 4)
void pconv_kernel(const float* __restrict__ x, const float* __restrict__ wg,
                  float* __restrict__ out) {
    // input tile, each element duplicated {v,v} for packed-broadcast LDS.128
    __shared__ __align__(16) float2 s_in[4 * 34 * PITCH];
    // weights: s_w[((tap*4 + m)*4 + g)*2 + e] = W[(g*8 + 2m + e)*36 + tap]
    __shared__ __align__(16) float s_w[1152];

    const int tid  = threadIdx.x;
    const int lane = tid & 31;
    const int wid8 = tid >> 5;            // warp id 0..7
    const int b   = blockIdx.z;
    const int h0  = blockIdx.y * 16;      // superpixel row base
    const int w0  = blockIdx.x * 16;      // superpixel col base
    const int py0 = 2 * h0 - 1;           // pixel row of tile row 0
    const int px0 = 2 * w0 - 1;

    // ---- stage weights (transposed/interleaved) ----
    for (int d = tid; d < 1152; d += 256) {
        int e = d & 1, g = (d >> 1) & 3, m = (d >> 3) & 3, tap = d >> 5;
        s_w[d] = wg[(g * 8 + 2 * m + e) * 36 + tap];
    }

    // ---- stage input tile (duplicated), warp-per-row, division-free ----
    const float* xb = x + (size_t)b * 4 * 512 * 512;
    #pragma unroll
    for (int cin = 0; cin < 4; cin++) {
        for (int r = wid8; r < 34; r += 8) {
            const int gr = py0 + r;
            const bool rowok = (unsigned)gr < 512u;
            const float* src = xb + ((size_t)cin * 512 + gr) * 512;
            float2* dst = &s_in[(cin * 34 + r) * PITCH];
            const int gc0 = px0 + lane;
            float v0 = 0.f;
            if (rowok && (unsigned)gc0 < 512u) v0 = src[gc0];
            dst[lane] = make_float2(v0, v0);
            if (lane < 2) {
                const int c1 = 32 + lane;
                const int gc1 = px0 + c1;
                float v1 = 0.f;
                if (rowok && (unsigned)gc1 < 512u) v1 = src[gc1];
                dst[c1] = make_float2(v1, v1);
            }
        }
    }
    __syncthreads();

    const int m   = tid & 3;
    const int tcx = (tid >> 2) & 3;
    const int ty  = tid >> 4;

    const float* s_wm = s_w + m * 8;   // weight base for this thread's m

    // acc[g][sp]: f32x2 = (out j=0, out j=1) for plane co = 2g + (m>>1),
    // out row 2*(h0+ty) + (m&1), superpixel x = w0 + 4*tcx + sp
    unsigned long long acc[4][4];
    #pragma unroll
    for (int g = 0; g < 4; g++)
        #pragma unroll
        for (int sp = 0; sp < 4; sp++)
            acc[g][sp] = 0ull;

    // apply row `row` to group-half gy (g = 2*gy, 2*gy+1) at tap row ky
    #define APPLY(GY, KY, CIN, ROW)                                         \
    {                                                                       \
        _Pragma("unroll")                                                   \
        for (int kx = 0; kx < 3; kx++) {                                    \
            const float* wb = s_wm + ((CIN) * 9 + (KY) * 3 + kx) * 32       \
                              + (GY) * 4;                                   \
            const ulonglong2 wp = *(const ulonglong2*)(wb);                 \
            _Pragma("unroll")                                               \
            for (int sp = 0; sp < 4; sp++) {                                \
                ffma2(acc[2 * (GY) + 0][sp], wp.x, (ROW)[2 * sp + 0 + kx]); \
                ffma2(acc[2 * (GY) + 1][sp], wp.y, (ROW)[2 * sp + 1 + kx]); \
            }                                                               \
        }                                                                   \
    }

    #pragma unroll
    for (int cin = 0; cin < 4; cin++) {
        const float2* rowbase = &s_in[(cin * 34 + 2 * ty) * PITCH + 8 * tcx];
        unsigned long long row[10];

        ldrow(row, rowbase);                 // r = 0
        APPLY(0, 0, cin, row)                //   gy=0, ky=0
        ldrow(row, rowbase + PITCH);         // r = 1
        APPLY(0, 1, cin, row)                //   gy=0, ky=1
        APPLY(1, 0, cin, row)                //   gy=1, ky=0
        ldrow(row, rowbase + 2 * PITCH);     // r = 2
        APPLY(0, 2, cin, row)                //   gy=0, ky=2
        APPLY(1, 1, cin, row)                //   gy=1, ky=1
        ldrow(row, rowbase + 3 * PITCH);     // r = 3
        APPLY(1, 2, cin, row)                //   gy=1, ky=2
    }
    #undef APPLY

    // ---- coalesced stores: per g, 8 consecutive px = 2x STG.128 ----
    float* ob = out + (size_t)b * 8 * 512 * 512;
    const int row_y = 2 * (h0 + ty) + (m & 1);
    const int colbase = 2 * w0 + 8 * tcx;
    #pragma unroll
    for (int g = 0; g < 4; g++) {
        const int co = 2 * g + (m >> 1);
        float* orow = ob + ((size_t)co * 512 + row_y) * 512 + colbase;
        ulonglong2 v0; v0.x = acc[g][0]; v0.y = acc[g][1];
        ulonglong2 v1; v1.x = acc[g][2]; v1.y = acc[g][3];
        *(ulonglong2*)(orow) = v0;
        *(ulonglong2*)(orow + 4) = v1;
    }
}

extern "C" void kernel_launch(void* const* d_in, const int* in_sizes, int n_in,
                              void* d_out, int out_size) {
    const float* x = (const float*)d_in[0];   // [8,4,512,512]
    const float* w = (const float*)d_in[1];   // [32,36,1,1]
    float* out = (float*)d_out;               // [8,8,512,512]
    dim3 grid(16, 16, 8);                     // 2048 blocks, 256 thr
    pconv_kernel<<<grid, 256>>>(x, w, out);
}